// round 4
// baseline (speedup 1.0000x reference)
#include <cuda_runtime.h>
#include <cuda_bf16.h>
#include <math.h>
#include <stdint.h>

// ---------------- problem constants ----------------
#define BATCH    512
#define SEQT     25
#define CH       512
#define NWIN     5
#define POOLW    5
#define BS       2560          // BATCH * NWIN
#define NROWS    5120          // 2 * BS
#define NT       40            // 128-row tiles per dim
#define TM       128
#define TEMP_INV 10.0f
#define SHIFT    10.0f
#define QSCALE   127.0f
#define LOGIT_SC (TEMP_INV / (QSCALE * QSCALE))   // int32 dot -> logit

// ---------------- device scratch ----------------
__device__ __align__(16) int8_t g_znq[NROWS * CH];  // normalized rows, int8 (2.5MB, L2-resident)
__device__ float g_rowS[NROWS];     // sum_j exp(logit-SHIFT), j != i
__device__ float g_rowPos[NROWS];   // positive logit per row

static __device__ __forceinline__ uint32_t smem_u32(const void* p) {
    uint32_t r;
    asm("{ .reg .u64 t; cvta.to.shared.u64 t, %1; cvt.u32.u64 %0, t; }" : "=r"(r) : "l"(p));
    return r;
}

#define LDSM_X4(R, addr) \
    asm volatile("ldmatrix.sync.aligned.m8n8.x4.shared.b16 {%0,%1,%2,%3}, [%4];" \
                 : "=r"((R)[0]), "=r"((R)[1]), "=r"((R)[2]), "=r"((R)[3]) : "r"(addr))

#define MMA16832(C, A, B0, B1) \
    asm volatile("mma.sync.aligned.m16n8k32.row.col.s32.s8.s8.s32 " \
                 "{%0,%1,%2,%3}, {%4,%5,%6,%7}, {%8,%9}, {%0,%1,%2,%3};" \
                 : "+r"((C)[0]), "+r"((C)[1]), "+r"((C)[2]), "+r"((C)[3]) \
                 : "r"((A)[0]), "r"((A)[1]), "r"((A)[2]), "r"((A)[3]), \
                   "r"(B0), "r"(B1))

// ---------------------------------------------------------------------------
// Kernel A: adaptive-avg-pool + L2 normalize -> int8 rows. Also zeros the
// row accumulators and the output (one block per row; must run every replay).
// ---------------------------------------------------------------------------
__global__ __launch_bounds__(128) void pool_norm_kernel(const float* __restrict__ zi,
                                                        const float* __restrict__ zj,
                                                        float* __restrict__ out) {
    int r  = blockIdx.x;
    if (threadIdx.x == 0) {
        g_rowS[r] = 0.0f;
        if (r == 0) out[0] = 0.0f;
    }
    const float* src = (r < BS) ? zi : zj;
    int rr = (r < BS) ? r : r - BS;
    int b  = rr / NWIN;
    int w  = rr % NWIN;
    const float* base = src + ((size_t)(b * SEQT + w * POOLW)) * CH;

    int c0 = threadIdx.x * 4;
    float4 acc = make_float4(0.f, 0.f, 0.f, 0.f);
#pragma unroll
    for (int t = 0; t < POOLW; t++) {
        float4 v = *(const float4*)(base + (size_t)t * CH + c0);
        acc.x += v.x; acc.y += v.y; acc.z += v.z; acc.w += v.w;
    }
    acc.x *= 0.2f; acc.y *= 0.2f; acc.z *= 0.2f; acc.w *= 0.2f;

    float ss = acc.x * acc.x + acc.y * acc.y + acc.z * acc.z + acc.w * acc.w;
#pragma unroll
    for (int o = 16; o > 0; o >>= 1) ss += __shfl_xor_sync(0xffffffffu, ss, o);

    __shared__ float wsum[4];
    if ((threadIdx.x & 31) == 0) wsum[threadIdx.x >> 5] = ss;
    __syncthreads();
    float tot = wsum[0] + wsum[1] + wsum[2] + wsum[3];

    float inv = QSCALE / fmaxf(sqrtf(tot), 1e-8f);
    int q0 = __float2int_rn(acc.x * inv);
    int q1 = __float2int_rn(acc.y * inv);
    int q2 = __float2int_rn(acc.z * inv);
    int q3 = __float2int_rn(acc.w * inv);
    uint32_t packed = (uint32_t)(q0 & 0xFF) | ((uint32_t)(q1 & 0xFF) << 8)
                    | ((uint32_t)(q2 & 0xFF) << 16) | ((uint32_t)(q3 & 0xFF) << 24);
    *(uint32_t*)(g_znq + (size_t)r * CH + c0) = packed;
}

// ---------------------------------------------------------------------------
// Kernel B: int8 IMMA Gram tiles (upper triangle) + fused exp / row+col sums.
// 256 threads, 8 warps; warp (wr=wid&3, wc=wid>>2) computes rows wr*32..+32,
// cols wc*64..+64 of the 128x128 tile. K chunks of 128 bytes in smem
// (row stride 144B -> conflict-free ldmatrix).
// ---------------------------------------------------------------------------
__global__ __launch_bounds__(256, 2) void simclr_imma_kernel() {
    int ct = blockIdx.x, rt = blockIdx.y;
    if (ct < rt) return;
    const bool diag = (ct == rt);
    const bool haspos = (ct == rt + 20);      // +BS = 20 tiles

    __shared__ __align__(16) int8_t As[TM * 144];
    __shared__ __align__(16) int8_t Bsm[TM * 144];
    __shared__ float rowsm[TM];
    __shared__ float colsm[TM];

    int tid = threadIdx.x;
    int wid = tid >> 5, lid = tid & 31;
    int wr = wid & 3, wc = wid >> 2;
    int g = lid >> 2, t4 = lid & 3;

    if (tid < TM) { rowsm[tid] = 0.f; colsm[tid] = 0.f; }

    int acc[2][8][4];
#pragma unroll
    for (int mi = 0; mi < 2; mi++)
#pragma unroll
        for (int na = 0; na < 8; na++)
#pragma unroll
            for (int q = 0; q < 4; q++) acc[mi][na][q] = 0;

    const int8_t* Ag = g_znq + (size_t)rt * TM * CH;
    const int8_t* Bg = g_znq + (size_t)ct * TM * CH;
    uint32_t aBase = smem_u32(As), bBase = smem_u32(Bsm);

    for (int k0 = 0; k0 < CH; k0 += 128) {
        __syncthreads();
#pragma unroll
        for (int it = 0; it < 4; it++) {
            int idx = tid + it * 256;            // 0..1023 (16B segments)
            int row = idx >> 3, ch = idx & 7;
            *(uint4*)(As  + row * 144 + ch * 16) =
                *(const uint4*)(Ag + (size_t)row * CH + k0 + ch * 16);
            *(uint4*)(Bsm + row * 144 + ch * 16) =
                *(const uint4*)(Bg + (size_t)row * CH + k0 + ch * 16);
        }
        __syncthreads();

#pragma unroll
        for (int ks = 0; ks < 4; ks++) {
            int kb = ks * 32;                    // byte offset in K
            uint32_t a[2][4];
#pragma unroll
            for (int mi = 0; mi < 2; mi++) {
                int r = wr * 32 + mi * 16 + (lid & 15);
                LDSM_X4(a[mi], aBase + r * 144 + kb + (lid >> 4) * 16);
            }
            uint32_t bfr[4][4];
#pragma unroll
            for (int nb = 0; nb < 4; nb++) {
                int r = wc * 64 + nb * 16 + (lid & 15);
                LDSM_X4(bfr[nb], bBase + r * 144 + kb + (lid >> 4) * 16);
            }
#pragma unroll
            for (int mi = 0; mi < 2; mi++)
#pragma unroll
                for (int na = 0; na < 8; na++)
                    MMA16832(acc[mi][na], a[mi], bfr[na >> 1][na & 1], bfr[na >> 1][2 + (na & 1)]);
        }
    }
    __syncthreads();

    // ---- fused epilogue ----
    int gr0 = rt * TM, gc0 = ct * TM;
    float colacc[16];
#pragma unroll
    for (int q = 0; q < 16; q++) colacc[q] = 0.f;
    float rowpart[2][2] = {{0.f, 0.f}, {0.f, 0.f}};

#pragma unroll
    for (int mi = 0; mi < 2; mi++) {
#pragma unroll
        for (int na = 0; na < 8; na++) {
#pragma unroll
            for (int q = 0; q < 4; q++) {
                int h = q >> 1, e = q & 1;
                int rl = wr * 32 + mi * 16 + g + h * 8;
                int cl = wc * 64 + na * 8 + t4 * 2 + e;
                float logit = (float)acc[mi][na][q] * LOGIT_SC;
                float ev = __expf(logit - SHIFT);
                if (diag && rl == cl) ev = 0.f;
                if (haspos && rl == cl) {
                    g_rowPos[gr0 + rl] = logit;
                    g_rowPos[gr0 + rl + BS] = logit;
                }
                rowpart[mi][h] += ev;
                colacc[na * 2 + e] += ev;
            }
        }
    }

    // row sums: reduce over t4 lanes (xor 1, 2)
#pragma unroll
    for (int mi = 0; mi < 2; mi++)
#pragma unroll
        for (int h = 0; h < 2; h++) {
            float v = rowpart[mi][h];
            v += __shfl_xor_sync(0xffffffffu, v, 1);
            v += __shfl_xor_sync(0xffffffffu, v, 2);
            if (t4 == 0) atomicAdd(&rowsm[wr * 32 + mi * 16 + g + h * 8], v);
        }

    // col sums: reduce over g lanes (xor 4, 8, 16)
#pragma unroll
    for (int q = 0; q < 16; q++) {
        float v = colacc[q];
        v += __shfl_xor_sync(0xffffffffu, v, 4);
        v += __shfl_xor_sync(0xffffffffu, v, 8);
        v += __shfl_xor_sync(0xffffffffu, v, 16);
        if (g == 0) atomicAdd(&colsm[wc * 64 + (q >> 1) * 8 + t4 * 2 + (q & 1)], v);
    }
    __syncthreads();

    if (tid < TM) {
        atomicAdd(&g_rowS[gr0 + tid], rowsm[tid]);
        if (!diag) atomicAdd(&g_rowS[gc0 + tid], colsm[tid]);
    }
}

// ---------------------------------------------------------------------------
// Kernel C: finalize. loss = (1/N) * sum_i [SHIFT + log(S_i) - pos_i]
// ---------------------------------------------------------------------------
__global__ __launch_bounds__(512) void finalize_kernel(float* __restrict__ out) {
    int i = blockIdx.x * 512 + threadIdx.x;
    float part = SHIFT + __logf(g_rowS[i]) - g_rowPos[i];

#pragma unroll
    for (int o = 16; o > 0; o >>= 1) part += __shfl_xor_sync(0xffffffffu, part, o);

    __shared__ float wsum[16];
    if ((threadIdx.x & 31) == 0) wsum[threadIdx.x >> 5] = part;
    __syncthreads();
    if (threadIdx.x == 0) {
        float tot = 0.f;
#pragma unroll
        for (int w = 0; w < 16; w++) tot += wsum[w];
        atomicAdd(out, tot / (float)NROWS);
    }
}

// ---------------------------------------------------------------------------
extern "C" void kernel_launch(void* const* d_in, const int* in_sizes, int n_in,
                              void* d_out, int out_size) {
    const float* zi = (const float*)d_in[0];
    const float* zj = (const float*)d_in[1];
    float* out = (float*)d_out;

    pool_norm_kernel<<<NROWS, 128>>>(zi, zj, out);
    dim3 grid(NT, NT);
    simclr_imma_kernel<<<grid, 256>>>();
    finalize_kernel<<<NROWS / 512, 512>>>(out);
}

// round 5
// speedup vs baseline: 1.4301x; 1.4301x over previous
#include <cuda_runtime.h>
#include <cuda_bf16.h>
#include <math.h>
#include <stdint.h>

// ---------------- problem constants ----------------
#define BATCH    512
#define SEQT     25
#define CH       512
#define NWIN     5
#define POOLW    5
#define BS       2560          // BATCH * NWIN
#define NROWS    5120          // 2 * BS
#define NT       40            // 128-row tiles per dim
#define TM       128
#define TEMP_INV 10.0f
#define SHIFT    10.0f
#define STRIDE_B 144           // padded smem row stride in bytes (64 bf16 + 8 pad)

// ---------------- device scratch ----------------
__device__ __align__(16) __nv_bfloat16 g_znh[NROWS * CH];  // normalized rows, bf16
__device__ float g_rowS[NROWS];     // sum_j exp(logit-SHIFT), j != i
__device__ float g_rowPos[NROWS];   // positive logit per row

static __device__ __forceinline__ uint32_t smem_u32(const void* p) {
    uint32_t r;
    asm("{ .reg .u64 t; cvta.to.shared.u64 t, %1; cvt.u32.u64 %0, t; }" : "=r"(r) : "l"(p));
    return r;
}

#define LDSM_X4(R, addr) \
    asm volatile("ldmatrix.sync.aligned.m8n8.x4.shared.b16 {%0,%1,%2,%3}, [%4];" \
                 : "=r"((R)[0]), "=r"((R)[1]), "=r"((R)[2]), "=r"((R)[3]) : "r"(addr))

#define MMA16816(C, A, B0, B1) \
    asm volatile("mma.sync.aligned.m16n8k16.row.col.f32.bf16.bf16.f32 " \
                 "{%0,%1,%2,%3}, {%4,%5,%6,%7}, {%8,%9}, {%0,%1,%2,%3};" \
                 : "+f"((C)[0]), "+f"((C)[1]), "+f"((C)[2]), "+f"((C)[3]) \
                 : "r"((A)[0]), "r"((A)[1]), "r"((A)[2]), "r"((A)[3]), \
                   "r"(B0), "r"(B1))

#define CP_ASYNC16(dst, src) \
    asm volatile("cp.async.cg.shared.global [%0], [%1], 16;" :: "r"(dst), "l"(src))
#define CP_COMMIT()  asm volatile("cp.async.commit_group;" ::: "memory")
#define CP_WAIT0()   asm volatile("cp.async.wait_group 0;" ::: "memory")

// ---------------------------------------------------------------------------
// Kernel A: adaptive-avg-pool + L2 normalize -> bf16 rows. Also zeros the
// row accumulators and the output (must run every replay).
// ---------------------------------------------------------------------------
__global__ __launch_bounds__(128) void pool_norm_kernel(const float* __restrict__ zi,
                                                        const float* __restrict__ zj,
                                                        float* __restrict__ out) {
    int r  = blockIdx.x;
    if (threadIdx.x == 0) {
        g_rowS[r] = 0.0f;
        if (r == 0) out[0] = 0.0f;
    }
    const float* src = (r < BS) ? zi : zj;
    int rr = (r < BS) ? r : r - BS;
    int b  = rr / NWIN;
    int w  = rr % NWIN;
    const float* base = src + ((size_t)(b * SEQT + w * POOLW)) * CH;

    int c0 = threadIdx.x * 4;
    float4 acc = make_float4(0.f, 0.f, 0.f, 0.f);
#pragma unroll
    for (int t = 0; t < POOLW; t++) {
        float4 v = *(const float4*)(base + (size_t)t * CH + c0);
        acc.x += v.x; acc.y += v.y; acc.z += v.z; acc.w += v.w;
    }
    acc.x *= 0.2f; acc.y *= 0.2f; acc.z *= 0.2f; acc.w *= 0.2f;

    float ss = acc.x * acc.x + acc.y * acc.y + acc.z * acc.z + acc.w * acc.w;
#pragma unroll
    for (int o = 16; o > 0; o >>= 1) ss += __shfl_xor_sync(0xffffffffu, ss, o);

    __shared__ float wsum[4];
    if ((threadIdx.x & 31) == 0) wsum[threadIdx.x >> 5] = ss;
    __syncthreads();
    float tot = wsum[0] + wsum[1] + wsum[2] + wsum[3];

    float inv = 1.0f / fmaxf(sqrtf(tot), 1e-8f);
    __nv_bfloat162 p0 = __floats2bfloat162_rn(acc.x * inv, acc.y * inv);
    __nv_bfloat162 p1 = __floats2bfloat162_rn(acc.z * inv, acc.w * inv);
    __nv_bfloat16* dst = g_znh + (size_t)r * CH + c0;
    *(__nv_bfloat162*)(dst)     = p0;
    *(__nv_bfloat162*)(dst + 2) = p1;
}

// ---------------------------------------------------------------------------
// Kernel B: HMMA bf16 Gram tiles (upper triangle) + fused exp / row+col sums.
// 256 threads, 8 warps; warp (wr=wid&3, wc=wid>>2) computes rows wr*32..+32,
// cols wc*64..+64. K chunks of 64 elems, DOUBLE-BUFFERED via cp.async.
// Dynamic smem: 2 x (A 128x144B + B 128x144B) = 73728 B.
// ---------------------------------------------------------------------------
__global__ __launch_bounds__(256, 2) void simclr_hmma_kernel() {
    int ct = blockIdx.x, rt = blockIdx.y;
    if (ct < rt) return;
    const bool diag = (ct == rt);
    const bool haspos = (ct == rt + 20);      // +BS = 20 tiles

    extern __shared__ __align__(16) char smem[];
    // buffer s: A at s*36864, B at s*36864 + 18432
    __shared__ float rowsm[TM];
    __shared__ float colsm[TM];

    int tid = threadIdx.x;
    int wid = tid >> 5, lid = tid & 31;
    int wr = wid & 3, wc = wid >> 2;
    int g = lid >> 2, t4 = lid & 3;

    if (tid < TM) { rowsm[tid] = 0.f; colsm[tid] = 0.f; }

    float acc[2][8][4];
#pragma unroll
    for (int mi = 0; mi < 2; mi++)
#pragma unroll
        for (int na = 0; na < 8; na++)
#pragma unroll
            for (int q = 0; q < 4; q++) acc[mi][na][q] = 0.f;

    const __nv_bfloat16* Ag = g_znh + (size_t)rt * TM * CH;
    const __nv_bfloat16* Bg = g_znh + (size_t)ct * TM * CH;
    uint32_t sbase = smem_u32(smem);

    // per-thread load slots: 4 A-segments + 4 B-segments of 16B per chunk
    int lrow = tid >> 1;               // 0..127
    int lch  = (tid & 1) * 4;          // 0 or 4 (16B units within 64-elem chunk)

    // prologue: load chunk 0 into buffer 0
#pragma unroll
    for (int u = 0; u < 4; u++) {
        CP_ASYNC16(sbase + lrow * STRIDE_B + (lch + u) * 16,
                   Ag + (size_t)lrow * CH + (lch + u) * 8);
        CP_ASYNC16(sbase + 18432 + lrow * STRIDE_B + (lch + u) * 16,
                   Bg + (size_t)lrow * CH + (lch + u) * 8);
    }
    CP_COMMIT();
    CP_WAIT0();
    __syncthreads();

    for (int c = 0; c < 8; c++) {
        uint32_t cur = sbase + (uint32_t)(c & 1) * 36864u;
        if (c < 7) {
            uint32_t nxt = sbase + (uint32_t)((c + 1) & 1) * 36864u;
            int k0 = (c + 1) * 64;
#pragma unroll
            for (int u = 0; u < 4; u++) {
                CP_ASYNC16(nxt + lrow * STRIDE_B + (lch + u) * 16,
                           Ag + (size_t)lrow * CH + k0 + (lch + u) * 8);
                CP_ASYNC16(nxt + 18432 + lrow * STRIDE_B + (lch + u) * 16,
                           Bg + (size_t)lrow * CH + k0 + (lch + u) * 8);
            }
            CP_COMMIT();
        }

        uint32_t aB = cur, bB = cur + 18432;
#pragma unroll
        for (int ks = 0; ks < 4; ks++) {
            int kk = ks * 16;
            uint32_t a[2][4];
#pragma unroll
            for (int mi = 0; mi < 2; mi++) {
                int r = wr * 32 + mi * 16 + (lid & 15);
                LDSM_X4(a[mi], aB + r * STRIDE_B + (kk + (lid >> 4) * 8) * 2);
            }
            uint32_t bfr[4][4];
#pragma unroll
            for (int nb = 0; nb < 4; nb++) {
                int r = wc * 64 + nb * 16 + (lid & 15);
                LDSM_X4(bfr[nb], bB + r * STRIDE_B + (kk + (lid >> 4) * 8) * 2);
            }
#pragma unroll
            for (int mi = 0; mi < 2; mi++)
#pragma unroll
                for (int na = 0; na < 8; na++)
                    MMA16816(acc[mi][na], a[mi], bfr[na >> 1][na & 1], bfr[na >> 1][2 + (na & 1)]);
        }

        if (c < 7) CP_WAIT0();
        __syncthreads();
    }

    // ---- fused epilogue ----
    int gr0 = rt * TM, gc0 = ct * TM;
    float colacc[16];
#pragma unroll
    for (int q = 0; q < 16; q++) colacc[q] = 0.f;
    float rowpart[2][2] = {{0.f, 0.f}, {0.f, 0.f}};

#pragma unroll
    for (int mi = 0; mi < 2; mi++) {
#pragma unroll
        for (int na = 0; na < 8; na++) {
#pragma unroll
            for (int q = 0; q < 4; q++) {
                int h = q >> 1, e = q & 1;
                int rl = wr * 32 + mi * 16 + g + h * 8;
                int cl = wc * 64 + na * 8 + t4 * 2 + e;
                float sim = acc[mi][na][q];
                float ev = __expf(sim * TEMP_INV - SHIFT);
                if (diag && rl == cl) ev = 0.f;
                if (haspos && rl == cl) {
                    float lg = sim * TEMP_INV;
                    g_rowPos[gr0 + rl] = lg;
                    g_rowPos[gr0 + rl + BS] = lg;
                }
                rowpart[mi][h] += ev;
                colacc[na * 2 + e] += ev;
            }
        }
    }

    // row sums: reduce over t4 lanes (xor 1, 2)
#pragma unroll
    for (int mi = 0; mi < 2; mi++)
#pragma unroll
        for (int h = 0; h < 2; h++) {
            float v = rowpart[mi][h];
            v += __shfl_xor_sync(0xffffffffu, v, 1);
            v += __shfl_xor_sync(0xffffffffu, v, 2);
            if (t4 == 0) atomicAdd(&rowsm[wr * 32 + mi * 16 + g + h * 8], v);
        }

    // col sums: reduce over g lanes (xor 4, 8, 16)
#pragma unroll
    for (int q = 0; q < 16; q++) {
        float v = colacc[q];
        v += __shfl_xor_sync(0xffffffffu, v, 4);
        v += __shfl_xor_sync(0xffffffffu, v, 8);
        v += __shfl_xor_sync(0xffffffffu, v, 16);
        if (g == 0) atomicAdd(&colsm[wc * 64 + (q >> 1) * 8 + t4 * 2 + (q & 1)], v);
    }
    __syncthreads();

    if (tid < TM) {
        atomicAdd(&g_rowS[gr0 + tid], rowsm[tid]);
        if (!diag) atomicAdd(&g_rowS[gc0 + tid], colsm[tid]);
    }
}

// ---------------------------------------------------------------------------
// Kernel C: finalize. loss = (1/N) * sum_i [SHIFT + log(S_i) - pos_i]
// ---------------------------------------------------------------------------
__global__ __launch_bounds__(512) void finalize_kernel(float* __restrict__ out) {
    int i = blockIdx.x * 512 + threadIdx.x;
    float part = SHIFT + __logf(g_rowS[i]) - g_rowPos[i];

#pragma unroll
    for (int o = 16; o > 0; o >>= 1) part += __shfl_xor_sync(0xffffffffu, part, o);

    __shared__ float wsum[16];
    if ((threadIdx.x & 31) == 0) wsum[threadIdx.x >> 5] = part;
    __syncthreads();
    if (threadIdx.x == 0) {
        float tot = 0.f;
#pragma unroll
        for (int w = 0; w < 16; w++) tot += wsum[w];
        atomicAdd(out, tot / (float)NROWS);
    }
}

// ---------------------------------------------------------------------------
extern "C" void kernel_launch(void* const* d_in, const int* in_sizes, int n_in,
                              void* d_out, int out_size) {
    const float* zi = (const float*)d_in[0];
    const float* zj = (const float*)d_in[1];
    float* out = (float*)d_out;

    cudaFuncSetAttribute(simclr_hmma_kernel,
                         cudaFuncAttributeMaxDynamicSharedMemorySize, 73728);

    pool_norm_kernel<<<NROWS, 128>>>(zi, zj, out);
    dim3 grid(NT, NT);
    simclr_hmma_kernel<<<grid, 256, 73728>>>();
    finalize_kernel<<<NROWS / 512, 512>>>(out);
}

// round 6
// speedup vs baseline: 1.7897x; 1.2515x over previous
#include <cuda_runtime.h>
#include <cuda_bf16.h>
#include <math.h>
#include <stdint.h>

// ---------------- problem constants ----------------
#define BATCH    512
#define SEQT     25
#define CH       512
#define NWIN     5
#define POOLW    5
#define BS       2560          // BATCH * NWIN
#define NROWS    5120          // 2 * BS
#define NT       40            // 128-row tiles per dim
#define NBLK     820           // NT*(NT+1)/2 upper-triangular tiles
#define TM       128
#define TEMP_INV 10.0f
#define SHIFT    10.0f

// ---------------- device scratch ----------------
__device__ __align__(16) __nv_bfloat16 g_znh[NROWS * CH];  // normalized rows, bf16
__device__ float g_rowS[NROWS];     // sum_j exp(logit-SHIFT), j != i
__device__ float g_rowPos[NROWS];   // positive logit per row

static __device__ __forceinline__ uint32_t smem_u32(const void* p) {
    uint32_t r;
    asm("{ .reg .u64 t; cvta.to.shared.u64 t, %1; cvt.u32.u64 %0, t; }" : "=r"(r) : "l"(p));
    return r;
}

#define LDSM_X4(R, addr) \
    asm volatile("ldmatrix.sync.aligned.m8n8.x4.shared.b16 {%0,%1,%2,%3}, [%4];" \
                 : "=r"((R)[0]), "=r"((R)[1]), "=r"((R)[2]), "=r"((R)[3]) : "r"(addr))

#define MMA16816(C, A, B0, B1) \
    asm volatile("mma.sync.aligned.m16n8k16.row.col.f32.bf16.bf16.f32 " \
                 "{%0,%1,%2,%3}, {%4,%5,%6,%7}, {%8,%9}, {%0,%1,%2,%3};" \
                 : "+f"((C)[0]), "+f"((C)[1]), "+f"((C)[2]), "+f"((C)[3]) \
                 : "r"((A)[0]), "r"((A)[1]), "r"((A)[2]), "r"((A)[3]), \
                   "r"(B0), "r"(B1))

// ---------------------------------------------------------------------------
// Kernel A: adaptive-avg-pool + L2 normalize -> bf16 rows. 2 rows per block.
// Also zeros row accumulators + output (must run every replay).
// ---------------------------------------------------------------------------
__global__ __launch_bounds__(256) void pool_norm_kernel(const float* __restrict__ zi,
                                                        const float* __restrict__ zj,
                                                        float* __restrict__ out) {
    int half = threadIdx.x >> 7;               // 0/1 : which row of this block
    int t    = threadIdx.x & 127;
    int r    = blockIdx.x * 2 + half;
    if (t == 0) {
        g_rowS[r] = 0.0f;
        if (r == 0) out[0] = 0.0f;
    }
    const float* src = (r < BS) ? zi : zj;
    int rr = (r < BS) ? r : r - BS;
    int b  = rr / NWIN;
    int w  = rr % NWIN;
    const float* base = src + ((size_t)(b * SEQT + w * POOLW)) * CH;

    int c0 = t * 4;
    float4 acc = make_float4(0.f, 0.f, 0.f, 0.f);
#pragma unroll
    for (int tt = 0; tt < POOLW; tt++) {
        float4 v = *(const float4*)(base + (size_t)tt * CH + c0);
        acc.x += v.x; acc.y += v.y; acc.z += v.z; acc.w += v.w;
    }
    acc.x *= 0.2f; acc.y *= 0.2f; acc.z *= 0.2f; acc.w *= 0.2f;

    float ss = acc.x * acc.x + acc.y * acc.y + acc.z * acc.z + acc.w * acc.w;
#pragma unroll
    for (int o = 16; o > 0; o >>= 1) ss += __shfl_xor_sync(0xffffffffu, ss, o);

    __shared__ float wsum[8];
    if ((threadIdx.x & 31) == 0) wsum[threadIdx.x >> 5] = ss;
    __syncthreads();
    float tot = wsum[half * 4] + wsum[half * 4 + 1] + wsum[half * 4 + 2] + wsum[half * 4 + 3];

    float inv = 1.0f / fmaxf(sqrtf(tot), 1e-8f);
    __nv_bfloat162 p0 = __floats2bfloat162_rn(acc.x * inv, acc.y * inv);
    __nv_bfloat162 p1 = __floats2bfloat162_rn(acc.z * inv, acc.w * inv);
    __nv_bfloat16* dst = g_znh + (size_t)r * CH + c0;
    *(__nv_bfloat162*)(dst)     = p0;
    *(__nv_bfloat162*)(dst + 2) = p1;
}

// ---------------------------------------------------------------------------
// Kernel B: HMMA bf16 Gram tiles (upper triangle, linearized grid of 820)
// + fused exp / row+col sums. 256 threads, 8 warps; warp (wr=wid&3, wc=wid>>2)
// computes rows wr*32..+32, cols wc*64..+64. K chunks of 64 staged in smem
// (row stride 144B -> conflict-free ldmatrix).
// ---------------------------------------------------------------------------
__global__ __launch_bounds__(256, 2) void simclr_hmma_kernel() {
    // decode linear block id -> (rt, ct) with ct >= rt
    int bid = blockIdx.x;
    int rt = (int)(0.5f * (81.0f - sqrtf(81.0f * 81.0f - 8.0f * (float)bid)));
    while ((rt + 1) * NT - ((rt + 1) * rt) / 2 <= bid) rt++;
    while (rt * NT - (rt * (rt - 1)) / 2 > bid) rt--;
    int ct = rt + bid - (rt * NT - (rt * (rt - 1)) / 2);

    const bool diag = (ct == rt);
    const bool haspos = (ct == rt + 20);      // +BS = 20 tiles

    __shared__ __align__(16) __nv_bfloat16 As[TM * 72];
    __shared__ __align__(16) __nv_bfloat16 Bsm[TM * 72];
    __shared__ float rowsm[TM];
    __shared__ float colsm[TM];

    int tid = threadIdx.x;
    int wid = tid >> 5, lid = tid & 31;
    int wr = wid & 3, wc = wid >> 2;
    int g = lid >> 2, t4 = lid & 3;

    if (tid < TM) { rowsm[tid] = 0.f; colsm[tid] = 0.f; }

    float acc[2][8][4];
#pragma unroll
    for (int mi = 0; mi < 2; mi++)
#pragma unroll
        for (int na = 0; na < 8; na++)
#pragma unroll
            for (int q = 0; q < 4; q++) acc[mi][na][q] = 0.f;

    const __nv_bfloat16* Ag = g_znh + (size_t)rt * TM * CH;
    const __nv_bfloat16* Bg = g_znh + (size_t)ct * TM * CH;
    uint32_t aBase = smem_u32(As), bBase = smem_u32(Bsm);

    for (int k0 = 0; k0 < CH; k0 += 64) {
        __syncthreads();
#pragma unroll
        for (int it = 0; it < 4; it++) {
            int idx = tid + it * 256;            // 0..1023 (16B segments)
            int row = idx >> 3, ch = idx & 7;
            *(uint4*)((char*)As  + row * 144 + ch * 16) =
                *(const uint4*)(Ag + (size_t)row * CH + k0 + ch * 8);
            *(uint4*)((char*)Bsm + row * 144 + ch * 16) =
                *(const uint4*)(Bg + (size_t)row * CH + k0 + ch * 8);
        }
        __syncthreads();

#pragma unroll
        for (int ks = 0; ks < 4; ks++) {
            int kk = ks * 16;
            uint32_t a[2][4];
#pragma unroll
            for (int mi = 0; mi < 2; mi++) {
                int r = wr * 32 + mi * 16 + (lid & 15);
                LDSM_X4(a[mi], aBase + r * 144 + (kk + (lid >> 4) * 8) * 2);
            }
            uint32_t bfr[4][4];
#pragma unroll
            for (int nb = 0; nb < 4; nb++) {
                int r = wc * 64 + nb * 16 + (lid & 15);
                LDSM_X4(bfr[nb], bBase + r * 144 + (kk + (lid >> 4) * 8) * 2);
            }
#pragma unroll
            for (int mi = 0; mi < 2; mi++)
#pragma unroll
                for (int na = 0; na < 8; na++)
                    MMA16816(acc[mi][na], a[mi], bfr[na >> 1][na & 1], bfr[na >> 1][2 + (na & 1)]);
        }
    }
    __syncthreads();

    // ---- fused epilogue ----
    int gr0 = rt * TM, gc0 = ct * TM;
    float colacc[16];
#pragma unroll
    for (int q = 0; q < 16; q++) colacc[q] = 0.f;
    float rowpart[2][2] = {{0.f, 0.f}, {0.f, 0.f}};

#pragma unroll
    for (int mi = 0; mi < 2; mi++) {
#pragma unroll
        for (int na = 0; na < 8; na++) {
#pragma unroll
            for (int q = 0; q < 4; q++) {
                int h = q >> 1, e = q & 1;
                int rl = wr * 32 + mi * 16 + g + h * 8;
                int cl = wc * 64 + na * 8 + t4 * 2 + e;
                float sim = acc[mi][na][q];
                float ev = __expf(sim * TEMP_INV - SHIFT);
                if (diag && rl == cl) ev = 0.f;
                if (haspos && rl == cl) {
                    float lg = sim * TEMP_INV;
                    g_rowPos[gr0 + rl] = lg;
                    g_rowPos[gr0 + rl + BS] = lg;
                }
                rowpart[mi][h] += ev;
                colacc[na * 2 + e] += ev;
            }
        }
    }

    // row sums: reduce over t4 lanes (xor 1, 2)
#pragma unroll
    for (int mi = 0; mi < 2; mi++)
#pragma unroll
        for (int h = 0; h < 2; h++) {
            float v = rowpart[mi][h];
            v += __shfl_xor_sync(0xffffffffu, v, 1);
            v += __shfl_xor_sync(0xffffffffu, v, 2);
            if (t4 == 0) atomicAdd(&rowsm[wr * 32 + mi * 16 + g + h * 8], v);
        }

    // col sums: reduce over g lanes (xor 4, 8, 16)
#pragma unroll
    for (int q = 0; q < 16; q++) {
        float v = colacc[q];
        v += __shfl_xor_sync(0xffffffffu, v, 4);
        v += __shfl_xor_sync(0xffffffffu, v, 8);
        v += __shfl_xor_sync(0xffffffffu, v, 16);
        if (g == 0) atomicAdd(&colsm[wc * 64 + (q >> 1) * 8 + t4 * 2 + (q & 1)], v);
    }
    __syncthreads();

    if (tid < TM) {
        atomicAdd(&g_rowS[gr0 + tid], rowsm[tid]);
        if (!diag) atomicAdd(&g_rowS[gc0 + tid], colsm[tid]);
    }
}

// ---------------------------------------------------------------------------
// Kernel C: finalize. loss = (1/N) * sum_i [SHIFT + log(S_i) - pos_i]
// ---------------------------------------------------------------------------
__global__ __launch_bounds__(256) void finalize_kernel(float* __restrict__ out) {
    int i = blockIdx.x * 256 + threadIdx.x;
    float part = SHIFT + __logf(g_rowS[i]) - g_rowPos[i];

#pragma unroll
    for (int o = 16; o > 0; o >>= 1) part += __shfl_xor_sync(0xffffffffu, part, o);

    __shared__ float wsum[8];
    if ((threadIdx.x & 31) == 0) wsum[threadIdx.x >> 5] = part;
    __syncthreads();
    if (threadIdx.x == 0) {
        float tot = 0.f;
#pragma unroll
        for (int w = 0; w < 8; w++) tot += wsum[w];
        atomicAdd(out, tot / (float)NROWS);
    }
}

// ---------------------------------------------------------------------------
extern "C" void kernel_launch(void* const* d_in, const int* in_sizes, int n_in,
                              void* d_out, int out_size) {
    const float* zi = (const float*)d_in[0];
    const float* zj = (const float*)d_in[1];
    float* out = (float*)d_out;

    pool_norm_kernel<<<NROWS / 2, 256>>>(zi, zj, out);
    simclr_hmma_kernel<<<NBLK, 256>>>();
    finalize_kernel<<<NROWS / 256, 256>>>(out);
}